// round 17
// baseline (speedup 1.0000x reference)
#include <cuda_runtime.h>
#include <cstdint>

// ExpandMask: x [B=64, 1, L=262144] f32 -> out [B, 1, 2L] float (0.0/1.0)
//   out[2i]   = (x[i-1] + x[i] + x[i+1] > 0.5)   (zero taps outside row)
//   out[2i+1] = (x[i]   + x[i+1]        > 0.5)
//
// FINAL (converged, R5-R16 campaign). Lane-interleaved coalesced layout:
// one output float4 per lane per chunk -> dense LDG.64 loads + dense
// STG.128 write-back stores; halo taps via warp shuffle, lane 0/31 edge
// taps via scalar loads. CHUNKS=2, BLOCK=256, regs=18.
//
// Roofline: ~144MB DRAM traffic per launch (128MB mandatory float32 output
// writes + ~15MB steady-state reads) at the measured ~5.0-5.1TB/s
// mixed-stream write-path ceiling. Eleven measurements across the full A/B
// matrix (store policy default/.cs/.wt, load policy default/.cs/nc/
// v8+evict_last, width 64/128/256b, MLP 2/4/8, block 256/1024) all land in
// a 28.2-29.2us kernel-time band -- the limiter is the DRAM write path,
// invariant to access shape. Only layout mattered (thread-blocked layouts
// suffer 2-4x L1 wavefront amplification).

static constexpr int L = 262144;                    // input row length
static constexpr int OUT_F4_PER_ROW = (2 * L) / 4;  // 131072 = 2^17
static constexpr int CHUNKS = 2;
static constexpr int BLOCK = 256;

__global__ void __launch_bounds__(BLOCK) expand_mask_kernel(
    const float* __restrict__ x, float4* __restrict__ out)
{
    const int lane = threadIdx.x & 31;
    const int block_base = blockIdx.x * (BLOCK * CHUNKS);

    // Front-batch independent dense float2 loads.
    int o[CHUNKS], ibase[CHUNKS], p[CHUNKS];
    float2 e[CHUNKS];
    #pragma unroll
    for (int c = 0; c < CHUNKS; c++) {
        o[c] = block_base + c * BLOCK + threadIdx.x;     // output float4 idx
        const int r = o[c] >> 17;                        // row (OUT_F4_PER_ROW = 2^17)
        p[c] = o[c] & (OUT_F4_PER_ROW - 1);              // position within row
        ibase[c] = r * L + 2 * p[c];                     // input float index
        e[c] = *reinterpret_cast<const float2*>(x + ibase[c]);
    }

    #pragma unroll
    for (int c = 0; c < CHUNKS; c++) {
        // Halo taps: left = x[2p-1], right = x[2p+2] (zero outside row).
        float left  = __shfl_up_sync(0xffffffffu, e[c].y, 1);
        float right = __shfl_down_sync(0xffffffffu, e[c].x, 1);
        if (lane == 0)
            left  = (p[c] == 0) ? 0.0f : __ldg(x + ibase[c] - 1);
        if (lane == 31)
            right = (p[c] == OUT_F4_PER_ROW - 1) ? 0.0f : __ldg(x + ibase[c] + 2);

        const float s01 = e[c].x + e[c].y;   // x[2p] + x[2p+1]
        float4 ov;
        ov.x = (left + s01)     > 0.5f ? 1.0f : 0.0f;  // out[4p]
        ov.y =  s01             > 0.5f ? 1.0f : 0.0f;  // out[4p+1]
        ov.z = (s01 + right)    > 0.5f ? 1.0f : 0.0f;  // out[4p+2]
        ov.w = (e[c].y + right) > 0.5f ? 1.0f : 0.0f;  // out[4p+3]

        out[o[c]] = ov;   // default write-back STG.128
    }
}

extern "C" void kernel_launch(void* const* d_in, const int* in_sizes, int n_in,
                              void* d_out, int out_size)
{
    const float* x = (const float*)d_in[0];
    float4* out = (float4*)d_out;

    const int total_out_f4 = (2 * in_sizes[0]) / 4;      // 8388608
    const int grid = total_out_f4 / (BLOCK * CHUNKS);    // 16384

    expand_mask_kernel<<<grid, BLOCK>>>(x, out);
}